// round 10
// baseline (speedup 1.0000x reference)
#include <cuda_runtime.h>
#include <cuda_fp16.h>
#include <cstdint>

// Problem constants
#define N_TOK 2048
#define D_IN  2048
#define D_OUT 2048
#define NE    8
#define NK    4096

// Tiling
#define BM 128
#define BN 128
#define KT 32
#define NT (D_IN / KT)
#define MAX_TILES 40

// smem: s_flat @0, A fp16 4 slots @1024, B fp16 2 slots after.
// Epilogue reuses [1024, 1024+32768) as the y transpose buffer.
#define SM_FLAT  0
#define A_OFF    1024
#define A_TILE   8192
#define B16_OFF  (A_OFF + 4 * A_TILE)      // 33792
#define B16_TILE 8192
#define SMEM_TOTAL (B16_OFF + 2 * B16_TILE)  // 50176 -> 2 CTA/SM
#define Y_OFF    1024                       // 32 KB, reused after main loop

// Device scratch
__device__ __half g_xh[(size_t)N_TOK * D_IN];   // 8 MB
__device__ __half g_yh[(size_t)NK * D_OUT];     // 16 MB

// 64B-row swizzle (validated R3-R9)
__device__ __forceinline__ uint32_t SW(uint32_t off) {
    return off ^ (((off >> 7) & 3u) << 4);
}

__device__ __forceinline__ uint32_t smem_u32(const void* p) {
    uint32_t a;
    asm("{ .reg .u64 t; cvta.to.shared.u64 t, %1; cvt.u32.u64 %0, t; }" : "=r"(a) : "l"(p));
    return a;
}

__device__ __forceinline__ void cp16(uint32_t dst, const void* src) {
    asm volatile("cp.async.cg.shared.global [%0], [%1], 16;" :: "r"(dst), "l"(src) : "memory");
}
__device__ __forceinline__ void cp_commit() {
    asm volatile("cp.async.commit_group;" ::: "memory");
}
__device__ __forceinline__ void cp_wait2() {
    asm volatile("cp.async.wait_group 2;" ::: "memory");
}

__device__ __forceinline__ void ldm_x4(uint32_t& r0, uint32_t& r1, uint32_t& r2,
                                       uint32_t& r3, uint32_t addr) {
    asm volatile("ldmatrix.sync.aligned.m8n8.x4.shared.b16 {%0,%1,%2,%3}, [%4];"
                 : "=r"(r0), "=r"(r1), "=r"(r2), "=r"(r3) : "r"(addr));
}

__device__ __forceinline__ void mma_fp16(float* c, const uint32_t* a, const uint32_t* b) {
    asm volatile(
        "mma.sync.aligned.m16n8k16.row.col.f32.f16.f16.f32 "
        "{%0,%1,%2,%3}, {%4,%5,%6,%7}, {%8,%9}, {%0,%1,%2,%3};"
        : "+f"(c[0]), "+f"(c[1]), "+f"(c[2]), "+f"(c[3])
        : "r"(a[0]), "r"(a[1]), "r"(a[2]), "r"(a[3]), "r"(b[0]), "r"(b[1]));
}

// ---------------------------------------------------------------------------
// Prepass: x fp32 -> fp16 (25 MB total, ~6 us)
// ---------------------------------------------------------------------------
__global__ void conv_x_kernel(const float* __restrict__ x) {
    size_t i = ((size_t)blockIdx.x * blockDim.x + threadIdx.x) * 8;
    float4 v0 = *(const float4*)(x + i);
    float4 v1 = *(const float4*)(x + i + 4);
    __half2 h[4];
    h[0] = __floats2half2_rn(v0.x, v0.y);
    h[1] = __floats2half2_rn(v0.z, v0.w);
    h[2] = __floats2half2_rn(v1.x, v1.y);
    h[3] = __floats2half2_rn(v1.z, v1.w);
    *(uint4*)(g_xh + i) = *(uint4*)h;
}

// ---------------------------------------------------------------------------
// Grouped GEMM with fused in-register W fp32->fp16 conversion.
// 128x128 tile/CTA, 4 warps (64x64 warp tile), A cp.async x4, B LDG+cvt+STS x2.
// ---------------------------------------------------------------------------
__global__ __launch_bounds__(128, 2)
void moe_gemm(const float* __restrict__ w,
              const int*   __restrict__ ssi,
              const int*   __restrict__ eoff) {
    const int tile = blockIdx.y;
    int e = -1, m0 = 0, rows = 0;
    {
        int nt = 0, prev = 0;
        #pragma unroll
        for (int ee = 0; ee < NE; ee++) {
            int end = __ldg(eoff + ee);
            int t = (end - prev + BM - 1) >> 7;
            if (e < 0 && tile < nt + t) {
                e = ee;
                m0 = prev + (tile - nt) * BM;
                int rem = end - m0;
                rows = rem < BM ? rem : BM;
            }
            nt += t;
            prev = end;
        }
    }
    if (e < 0) return;
    const int n0 = blockIdx.x * BN;

    extern __shared__ char smem[];
    const uint32_t sb = smem_u32(smem);
    const int tid  = threadIdx.x;
    const int wid  = tid >> 5;
    const int lane = tid & 31;
    const int warp_m = wid & 1;
    const int warp_n = wid >> 1;

    int* s_flat = (int*)(smem + SM_FLAT);
    if (tid < BM) s_flat[tid] = (tid < rows) ? ssi[m0 + tid] : -1;
    __syncthreads();

    // --- A cp.async mapping: thread owns chunks {tid + 128q}, q=0..3 ---
    const int c16 = (tid & 3) * 8;
    const __half* aptr[4];
    uint32_t dofsA[4];
    #pragma unroll
    for (int q = 0; q < 4; q++) {
        const int r = (tid >> 2) + 32 * q;
        const int fl = s_flat[r];
        const int tk = (fl >= 0 ? fl : 0) >> 1;
        aptr[q] = g_xh + (size_t)tk * D_IN + c16;
        dofsA[q] = SW((uint32_t)(r * 64 + (tid & 3) * 16));
    }

    // --- B fp32 loader: thread owns B row `tid` (32 floats per k-tile) ---
    const float* wrow = w + ((size_t)e * D_OUT + (size_t)(n0 + tid)) * D_IN;
    uint32_t bsts[4];
    #pragma unroll
    for (int c = 0; c < 4; c++) bsts[c] = SW((uint32_t)(tid * 64 + c * 16));

    // ldmatrix offsets (proven layout)
    uint32_t a_off[2][4], b_off[2][4];
    #pragma unroll
    for (int s = 0; s < 2; s++) {
        #pragma unroll
        for (int i = 0; i < 4; i++) {
            int arow = warp_m * 64 + i * 16 + (lane & 7) + ((lane >> 3) & 1) * 8;
            int ach  = s * 2 + (lane >> 4);
            a_off[s][i] = SW((uint32_t)(arow * 64 + ach * 16));
        }
        #pragma unroll
        for (int jp = 0; jp < 4; jp++) {
            int brow = warp_n * 64 + (jp * 2 + (lane >> 4)) * 8 + (lane & 7);
            int bch  = s * 2 + ((lane >> 3) & 1);
            b_off[s][jp] = SW((uint32_t)(brow * 64 + bch * 16));
        }
    }

    auto issueA = [&](int kt) {
        const uint32_t stg = sb + A_OFF + (uint32_t)(kt & 3) * A_TILE;
        const int k = kt * KT;
        #pragma unroll
        for (int q = 0; q < 4; q++) cp16(stg + dofsA[q], aptr[q] + k);
    };

    float4 vb[8];   // 32 fp32: this thread's B row slice for one k-tile
    auto ldgB = [&](int kt) {
        const float4* p = (const float4*)(wrow + kt * KT);
        #pragma unroll
        for (int q = 0; q < 8; q++) vb[q] = p[q];
    };
    auto stsB = [&](int kt) {
        const uint32_t base = sb + B16_OFF + (uint32_t)(kt & 1) * B16_TILE;
        #pragma unroll
        for (int c = 0; c < 4; c++) {
            __half2 h0 = __floats2half2_rn(vb[2 * c].x,     vb[2 * c].y);
            __half2 h1 = __floats2half2_rn(vb[2 * c].z,     vb[2 * c].w);
            __half2 h2 = __floats2half2_rn(vb[2 * c + 1].x, vb[2 * c + 1].y);
            __half2 h3 = __floats2half2_rn(vb[2 * c + 1].z, vb[2 * c + 1].w);
            asm volatile("st.shared.v4.b32 [%0], {%1,%2,%3,%4};" :: "r"(base + bsts[c]),
                "r"(*(uint32_t*)&h0), "r"(*(uint32_t*)&h1),
                "r"(*(uint32_t*)&h2), "r"(*(uint32_t*)&h3) : "memory");
        }
    };

    float acc[4][8][4];
    #pragma unroll
    for (int i = 0; i < 4; i++)
        #pragma unroll
        for (int j = 0; j < 8; j++)
            #pragma unroll
            for (int q = 0; q < 4; q++) acc[i][j][q] = 0.0f;

    // Prologue: A tiles 0..2 in flight; B tile 0 converted into slot 0
    issueA(0); cp_commit();
    issueA(1); cp_commit();
    issueA(2); cp_commit();
    ldgB(0); stsB(0);

    for (int it = 0; it < NT; it++) {
        cp_wait2();          // A(it) landed
        __syncthreads();     // orders prior STS(B16) + all reads of reused slots

        if (it + 3 < NT) issueA(it + 3);
        cp_commit();
        if (it + 1 < NT) ldgB(it + 1);   // latency hidden under compute below

        const uint32_t stga = sb + A_OFF + (uint32_t)(it & 3) * A_TILE;
        const uint32_t stgb = sb + B16_OFF + (uint32_t)(it & 1) * B16_TILE;
        #pragma unroll
        for (int s = 0; s < 2; s++) {
            uint32_t ah[4][4], bh[4][4];
            #pragma unroll
            for (int i = 0; i < 4; i++)
                ldm_x4(ah[i][0], ah[i][1], ah[i][2], ah[i][3], stga + a_off[s][i]);
            #pragma unroll
            for (int jp = 0; jp < 4; jp++)
                ldm_x4(bh[jp][0], bh[jp][1], bh[jp][2], bh[jp][3], stgb + b_off[s][jp]);
            #pragma unroll
            for (int i = 0; i < 4; i++) {
                #pragma unroll
                for (int jp = 0; jp < 4; jp++) {
                    mma_fp16(acc[i][2 * jp],     ah[i], &bh[jp][0]);
                    mma_fp16(acc[i][2 * jp + 1], ah[i], &bh[jp][2]);
                }
            }
        }
        if (it + 1 < NT) stsB(it + 1);   // into slot (it+1)&1, read next iter
    }

    // ---- Epilogue: transpose through smem, then contiguous 256B row stores ----
    __syncthreads();   // everyone done with A/B smem; reuse as y buffer
    char* ys = smem + Y_OFF;
    #pragma unroll
    for (int i = 0; i < 4; i++) {
        const int mr0 = warp_m * 64 + i * 16 + (lane >> 2);
        #pragma unroll
        for (int j = 0; j < 8; j++) {
            const int ch = warp_n * 8 + j;
            __half2 v0 = __floats2half2_rn(acc[i][j][0], acc[i][j][1]);
            __half2 v1 = __floats2half2_rn(acc[i][j][2], acc[i][j][3]);
            const int mr1 = mr0 + 8;
            *(uint32_t*)(ys + mr0 * 256 + ((ch ^ (mr0 & 15)) << 4) + (lane & 3) * 4) =
                *(uint32_t*)&v0;
            *(uint32_t*)(ys + mr1 * 256 + ((ch ^ (mr1 & 15)) << 4) + (lane & 3) * 4) =
                *(uint32_t*)&v1;
        }
    }
    __syncthreads();
    {
        const int fl = s_flat[tid];
        if (fl >= 0) {
            __half* dst = g_yh + (size_t)fl * D_OUT + n0;
            #pragma unroll
            for (int q = 0; q < 16; q++) {
                uint4 v = *(uint4*)(ys + tid * 256 + ((q ^ (tid & 15)) << 4));
                *(uint4*)(dst + q * 8) = v;
            }
        }
    }
}

// ---------------------------------------------------------------------------
// Combine (fp16 y): out[n, :] = g0*y[2n, :] + g1*y[2n+1, :]
// ---------------------------------------------------------------------------
__global__ void combine_kernel(const float* __restrict__ gates,
                               float* __restrict__ out) {
    int idx = blockIdx.x * blockDim.x + threadIdx.x;
    int n  = idx >> 8;
    int d8 = idx & 255;
    float g0 = gates[2 * n];
    float g1 = gates[2 * n + 1];
    const uint4 ya = *(const uint4*)(g_yh + (size_t)(2 * n)     * D_OUT + d8 * 8);
    const uint4 yb = *(const uint4*)(g_yh + (size_t)(2 * n + 1) * D_OUT + d8 * 8);
    const __half2* ha = (const __half2*)&ya;
    const __half2* hb = (const __half2*)&yb;
    float4 o[2];
    #pragma unroll
    for (int q = 0; q < 2; q++) {
        float2 a0 = __half22float2(ha[2 * q]);
        float2 a1 = __half22float2(ha[2 * q + 1]);
        float2 b0 = __half22float2(hb[2 * q]);
        float2 b1 = __half22float2(hb[2 * q + 1]);
        o[q] = make_float4(g0 * a0.x + g1 * b0.x, g0 * a0.y + g1 * b0.y,
                           g0 * a1.x + g1 * b1.x, g0 * a1.y + g1 * b1.y);
    }
    float4* dst = (float4*)(out + (size_t)n * D_OUT + d8 * 8);
    dst[0] = o[0];
    dst[1] = o[1];
}

// ---------------------------------------------------------------------------
extern "C" void kernel_launch(void* const* d_in, const int* in_sizes, int n_in,
                              void* d_out, int out_size) {
    const float* x     = (const float*)d_in[0];
    const float* w     = (const float*)d_in[1];
    const int*   ssi   = (const int*)  d_in[4];
    const int*   eoff  = (const int*)  d_in[6];
    const float* gates = (const float*)d_in[7];
    float* out = (float*)d_out;

    conv_x_kernel<<<(N_TOK * D_IN) / (256 * 8), 256>>>(x);

    cudaFuncSetAttribute(moe_gemm,
                         cudaFuncAttributeMaxDynamicSharedMemorySize, SMEM_TOTAL);
    dim3 grid(D_OUT / BN, MAX_TILES);
    moe_gemm<<<grid, 128, SMEM_TOTAL>>>(w, ssi, eoff);

    combine_kernel<<<(N_TOK * (D_OUT / 8)) / 256, 256>>>(gates, out);
}

// round 12
// speedup vs baseline: 1.4601x; 1.4601x over previous
#include <cuda_runtime.h>
#include <cuda_fp16.h>
#include <cstdint>

// Problem constants
#define N_TOK 2048
#define D_IN  2048
#define D_OUT 2048
#define NE    8
#define NK    4096

// Tiling
#define BM 128
#define BN 128
#define KT 32
#define NT (D_IN / KT)
#define MAX_TILES 40

// smem layout (bytes)
#define SM_FLAT  0
#define A_OFF    1024
#define A_TILE   8192                       // fp16 A, 4 slots
#define B16_OFF  (A_OFF + 4 * A_TILE)       // 33792, fp16 B, 3 slots
#define B16_TILE 8192
#define B32_OFF  (B16_OFF + 3 * B16_TILE)   // 58368, fp32 B, 3 slots
#define B32_TILE 16384
#define SMEM_TOTAL (B32_OFF + 3 * B32_TILE) // 107520 -> 2 CTA/SM

// Device scratch
__device__ __half g_xh[(size_t)N_TOK * D_IN];   // 8 MB
__device__ float  g_y[(size_t)NK * D_OUT];      // 32 MB

// 64B-row swizzle (validated R3-R10)
__device__ __forceinline__ uint32_t SW(uint32_t off) {
    return off ^ (((off >> 7) & 3u) << 4);
}

__device__ __forceinline__ uint32_t smem_u32(const void* p) {
    uint32_t a;
    asm("{ .reg .u64 t; cvta.to.shared.u64 t, %1; cvt.u32.u64 %0, t; }" : "=r"(a) : "l"(p));
    return a;
}

__device__ __forceinline__ void cp16(uint32_t dst, const void* src) {
    asm volatile("cp.async.cg.shared.global [%0], [%1], 16;" :: "r"(dst), "l"(src) : "memory");
}
__device__ __forceinline__ void cp_commit() {
    asm volatile("cp.async.commit_group;" ::: "memory");
}
__device__ __forceinline__ void cp_wait2() {
    asm volatile("cp.async.wait_group 2;" ::: "memory");
}

__device__ __forceinline__ void ldm_x4(uint32_t& r0, uint32_t& r1, uint32_t& r2,
                                       uint32_t& r3, uint32_t addr) {
    asm volatile("ldmatrix.sync.aligned.m8n8.x4.shared.b16 {%0,%1,%2,%3}, [%4];"
                 : "=r"(r0), "=r"(r1), "=r"(r2), "=r"(r3) : "r"(addr));
}

__device__ __forceinline__ void mma_fp16(float* c, const uint32_t* a, const uint32_t* b) {
    asm volatile(
        "mma.sync.aligned.m16n8k16.row.col.f32.f16.f16.f32 "
        "{%0,%1,%2,%3}, {%4,%5,%6,%7}, {%8,%9}, {%0,%1,%2,%3};"
        : "+f"(c[0]), "+f"(c[1]), "+f"(c[2]), "+f"(c[3])
        : "r"(a[0]), "r"(a[1]), "r"(a[2]), "r"(a[3]), "r"(b[0]), "r"(b[1]));
}

// ---------------------------------------------------------------------------
// Prepass: x fp32 -> fp16 (25 MB, ~6.5 us)
// ---------------------------------------------------------------------------
__global__ void conv_x_kernel(const float* __restrict__ x) {
    size_t i = ((size_t)blockIdx.x * blockDim.x + threadIdx.x) * 8;
    float4 v0 = *(const float4*)(x + i);
    float4 v1 = *(const float4*)(x + i + 4);
    __half2 h[4];
    h[0] = __floats2half2_rn(v0.x, v0.y);
    h[1] = __floats2half2_rn(v0.z, v0.w);
    h[2] = __floats2half2_rn(v1.x, v1.y);
    h[3] = __floats2half2_rn(v1.z, v1.w);
    *(uint4*)(g_xh + i) = *(uint4*)h;
}

// ---------------------------------------------------------------------------
// Grouped GEMM with fused W fp32->fp16 (cp.async fp32 B ring, convert after
// compute, race fixed by a wait BEFORE convert). 128x128 tile, 4 warps.
// ---------------------------------------------------------------------------
__global__ __launch_bounds__(128, 2)
void moe_gemm(const float* __restrict__ w,
              const int*   __restrict__ ssi,
              const int*   __restrict__ eoff) {
    const int tile = blockIdx.y;
    int e = -1, m0 = 0, rows = 0;
    {
        int nt = 0, prev = 0;
        #pragma unroll
        for (int ee = 0; ee < NE; ee++) {
            int end = __ldg(eoff + ee);
            int t = (end - prev + BM - 1) >> 7;
            if (e < 0 && tile < nt + t) {
                e = ee;
                m0 = prev + (tile - nt) * BM;
                int rem = end - m0;
                rows = rem < BM ? rem : BM;
            }
            nt += t;
            prev = end;
        }
    }
    if (e < 0) return;
    const int n0 = blockIdx.x * BN;

    extern __shared__ char smem[];
    const uint32_t sb = smem_u32(smem);
    const int tid  = threadIdx.x;
    const int wid  = tid >> 5;
    const int lane = tid & 31;
    const int warp_m = wid & 1;
    const int warp_n = wid >> 1;

    int* s_flat = (int*)(smem + SM_FLAT);
    if (tid < BM) s_flat[tid] = (tid < rows) ? ssi[m0 + tid] : -1;
    __syncthreads();

    // A cp.async mapping: thread owns chunks {tid + 128q}, q=0..3
    const int c16 = (tid & 3) * 8;
    const __half* aptr[4];
    uint32_t dofsA[4];
    #pragma unroll
    for (int q = 0; q < 4; q++) {
        const int r = (tid >> 2) + 32 * q;
        const int fl = s_flat[r];
        const int tk = (fl >= 0 ? fl : 0) >> 1;
        aptr[q] = g_xh + (size_t)tk * D_IN + c16;
        dofsA[q] = SW((uint32_t)(r * 64 + (tid & 3) * 16));
    }

    // B fp32 cp.async: thread owns chunks {tid + 128q}, q=0..7 (linear layout)
    const float* wbase = w + ((size_t)e * D_OUT + (size_t)(n0 + (tid >> 3))) * D_IN
                           + (tid & 7) * 4;

    // ldmatrix offsets (proven layout)
    uint32_t a_off[2][4], b_off[2][4];
    #pragma unroll
    for (int s = 0; s < 2; s++) {
        #pragma unroll
        for (int i = 0; i < 4; i++) {
            int arow = warp_m * 64 + i * 16 + (lane & 7) + ((lane >> 3) & 1) * 8;
            int ach  = s * 2 + (lane >> 4);
            a_off[s][i] = SW((uint32_t)(arow * 64 + ach * 16));
        }
        #pragma unroll
        for (int jp = 0; jp < 4; jp++) {
            int brow = warp_n * 64 + (jp * 2 + (lane >> 4)) * 8 + (lane & 7);
            int bch  = s * 2 + ((lane >> 3) & 1);
            b_off[s][jp] = SW((uint32_t)(brow * 64 + bch * 16));
        }
    }

    auto issue = [&](int kt) {
        const uint32_t abase = sb + A_OFF + (uint32_t)(kt & 3) * A_TILE;
        const int k = kt * KT;
        #pragma unroll
        for (int q = 0; q < 4; q++) cp16(abase + dofsA[q], aptr[q] + k);
        const uint32_t bbase = sb + B32_OFF + (uint32_t)(kt % 3) * B32_TILE;
        const float* ws = wbase + k;
        #pragma unroll
        for (int q = 0; q < 8; q++)
            cp16(bbase + (uint32_t)(tid + 128 * q) * 16, ws + (size_t)(16 * q) * D_IN);
    };

    auto convert = [&](int kt) {
        const char* b32 = smem + B32_OFF + (kt % 3) * B32_TILE;
        char* b16 = smem + B16_OFF + (kt % 3) * B16_TILE;
        #pragma unroll
        for (int q = 0; q < 8; q++) {
            const int ch = tid + 128 * q;
            float4 v = *(const float4*)(b32 + ch * 16);
            __half2 h0 = __floats2half2_rn(v.x, v.y);
            __half2 h1 = __floats2half2_rn(v.z, v.w);
            const int row = (tid >> 3) + 16 * q;
            uint32_t off = SW((uint32_t)(row * 64 + (tid & 7) * 8));
            *(uint2*)(b16 + off) = make_uint2(*(uint32_t*)&h0, *(uint32_t*)&h1);
        }
    };

    float acc[4][8][4];
    #pragma unroll
    for (int i = 0; i < 4; i++)
        #pragma unroll
        for (int j = 0; j < 8; j++)
            #pragma unroll
            for (int q = 0; q < 4; q++) acc[i][j][q] = 0.0f;

    // Prologue: tiles 0,1,2 in flight; convert tile 0 once it lands
    issue(0); cp_commit();
    issue(1); cp_commit();
    issue(2); cp_commit();
    cp_wait2();            // 3 groups committed, <=2 pending -> tile 0 landed
    convert(0);

    for (int it = 0; it < NT; it++) {
        // Top: groups committed = it+3 (plus waits below already satisfied more).
        cp_wait2();        // tiles <= it landed: A(it)/B32(it) resident
        __syncthreads();   // closes prior convert STS + prior iter slot reads

        if (it + 3 < NT) issue(it + 3);
        cp_commit();

        const uint32_t stga = sb + A_OFF + (uint32_t)(it & 3) * A_TILE;
        const uint32_t stgb = sb + B16_OFF + (uint32_t)(it % 3) * B16_TILE;
        #pragma unroll
        for (int s = 0; s < 2; s++) {
            uint32_t ah[4][4], bh[4][4];
            #pragma unroll
            for (int i = 0; i < 4; i++)
                ldm_x4(ah[i][0], ah[i][1], ah[i][2], ah[i][3], stga + a_off[s][i]);
            #pragma unroll
            for (int jp = 0; jp < 4; jp++)
                ldm_x4(bh[jp][0], bh[jp][1], bh[jp][2], bh[jp][3], stgb + b_off[s][jp]);
            #pragma unroll
            for (int i = 0; i < 4; i++) {
                #pragma unroll
                for (int jp = 0; jp < 4; jp++) {
                    mma_fp16(acc[i][2 * jp],     ah[i], &bh[jp][0]);
                    mma_fp16(acc[i][2 * jp + 1], ah[i], &bh[jp][2]);
                }
            }
        }

        // RACE FIX (R11 bug): ensure tile it+1 has LANDED before converting it.
        // After this iter's commit, groups = it+4; wait2 -> completed >= it+2
        // -> tiles 0..it+1 resident. Usually already satisfied (issued 3 iters ago).
        if (it + 1 < NT) {
            cp_wait2();
            convert(it + 1);   // B16 slot (it+1)%3: not read this iter, read next
        }
    }

    // Epilogue (R6-proven): scatter fp32 y
    #pragma unroll
    for (int i = 0; i < 4; i++) {
        const int mr0 = warp_m * 64 + i * 16 + (lane >> 2);
        const int fl0 = s_flat[mr0];
        const int fl1 = s_flat[mr0 + 8];
        #pragma unroll
        for (int j = 0; j < 8; j++) {
            const int col = n0 + warp_n * 64 + j * 8 + (lane & 3) * 2;
            if (fl0 >= 0)
                *(float2*)(g_y + (size_t)fl0 * D_OUT + col) =
                    make_float2(acc[i][j][0], acc[i][j][1]);
            if (fl1 >= 0)
                *(float2*)(g_y + (size_t)fl1 * D_OUT + col) =
                    make_float2(acc[i][j][2], acc[i][j][3]);
        }
    }
}

// ---------------------------------------------------------------------------
__global__ void combine_kernel(const float* __restrict__ gates,
                               float* __restrict__ out) {
    int idx = blockIdx.x * blockDim.x + threadIdx.x;
    int n  = idx >> 9;
    int d4 = idx & 511;
    float g0 = gates[2 * n];
    float g1 = gates[2 * n + 1];
    const float4* y0 = (const float4*)(g_y + (size_t)(2 * n)     * D_OUT) + d4;
    const float4* y1 = (const float4*)(g_y + (size_t)(2 * n + 1) * D_OUT) + d4;
    float4 a = *y0, b = *y1, o;
    o.x = g0 * a.x + g1 * b.x;
    o.y = g0 * a.y + g1 * b.y;
    o.z = g0 * a.z + g1 * b.z;
    o.w = g0 * a.w + g1 * b.w;
    ((float4*)out)[idx] = o;
}

// ---------------------------------------------------------------------------
extern "C" void kernel_launch(void* const* d_in, const int* in_sizes, int n_in,
                              void* d_out, int out_size) {
    const float* x     = (const float*)d_in[0];
    const float* w     = (const float*)d_in[1];
    const int*   ssi   = (const int*)  d_in[4];
    const int*   eoff  = (const int*)  d_in[6];
    const float* gates = (const float*)d_in[7];
    float* out = (float*)d_out;

    conv_x_kernel<<<(N_TOK * D_IN) / (256 * 8), 256>>>(x);

    cudaFuncSetAttribute(moe_gemm,
                         cudaFuncAttributeMaxDynamicSharedMemorySize, SMEM_TOTAL);
    dim3 grid(D_OUT / BN, MAX_TILES);
    moe_gemm<<<grid, 128, SMEM_TOTAL>>>(w, ssi, eoff);

    combine_kernel<<<(N_TOK * (D_OUT / 4)) / 256, 256>>>(gates, out);
}